// round 8
// baseline (speedup 1.0000x reference)
#include <cuda_runtime.h>
#include <cuda_bf16.h>

// LSTM decoder, B=1024, S=256, H=128, O=7, T=512.
//  - gates = h @ (W_ih + W_hh).T + (b_ih + b_hh)   (both matmuls use h!)
//  - recurrence independent across batch -> persistent kernel, no global sync.
//
// Split-K occupancy kernel. 128 CTAs x 512 threads (16 warps, 4/SMSP).
// Thread (hidx, ghalf, khalf): computes TWO gates for hidden unit hidx over
// 8 batch rows, for HALF of the k range (64 of 128):
//   ghalf 0: gates i,f (SMEM weights)   ghalf 1: gate g (SMEM) + o (L2 stream)
// Partials combined in a unified SMEM gate buffer gb[gate][row][hidx]:
//   khalf=1 writes partials; khalf=0 adds own partial + bias (RMW).
// Pointwise c/h update spread over ALL 16 warps (2 rows/thread; c-state
// register-resident per owner thread). Output projection (224 thr) reads h
// and a transposed W_out copy from SMEM, both conflict-free.

#define B_   1024
#define S_   256
#define H_   128
#define O_   7

// combined weights in [gate][k4][hidx][kk] layout (k packed in float4)
__device__ float g_Wc[4 * 32 * 128 * 4];
__device__ float g_bc[512];

__global__ void prep_kernel(const float* __restrict__ Wih,
                            const float* __restrict__ Whh,
                            const float* __restrict__ bih,
                            const float* __restrict__ bhh) {
    int idx = blockIdx.x * blockDim.x + threadIdx.x;  // over 512*128
    if (idx < 512 * 128) {
        int j = idx >> 7;        // gate-row 0..511
        int k = idx & 127;       // input hidden idx
        float w = Wih[idx] + Whh[idx];
        int g = j >> 7;
        int h = j & 127;
        g_Wc[(((g * 32) + (k >> 2)) * 128 + h) * 4 + (k & 3)] = w;
    }
    if (idx < 512) g_bc[idx] = bih[idx] + bhh[idx];
}

__device__ __forceinline__ void fma2(unsigned long long& d,
                                     unsigned long long a,
                                     unsigned long long b) {
    asm("fma.rn.f32x2 %0, %1, %2, %0;" : "+l"(d) : "l"(a), "l"(b));
}

__device__ __forceinline__ float redu(unsigned long long v) {
    float2 f = *reinterpret_cast<float2*>(&v);
    return f.x + f.y;
}

__device__ __forceinline__ float sigf(float x) {
    // 1/(1+e^-x): safe at both extremes
    return __fdividef(1.0f, 1.0f + __expf(-x));
}

__device__ __forceinline__ float tanhf_fast(float x) {
    // 1 - 2/(e^{2x}+1): safe at both extremes
    return 1.0f - __fdividef(2.0f, __expf(2.0f * x) + 1.0f);
}

// dynamic smem layout (floats):
//   sW   : 3*32*128*4 = 49152  (gates i,f,g weights)
//   sh   : 2*8*132    = 2112   (double-buffered h, padded stride 132)
//   gb   : 4*8*128    = 4096   (gate values: [gate][row][hidx])
//   sWoT : 32*28      = 896    (W_out transposed: [m][po*4+ppart])
#define SW_FLOATS  49152
#define SH_FLOATS  2112
#define GB_FLOATS  4096
#define SWO_FLOATS 896
#define SMEM_FLOATS (SW_FLOATS + SH_FLOATS + GB_FLOATS + SWO_FLOATS)

// gate inner-product body over one k4 chunk (8 rows, 2 gates)
#define GATE_K4(KK, WA, WB)                                                \
    {                                                                      \
        ulonglong2 h4[8];                                                  \
        _Pragma("unroll")                                                  \
        for (int r = 0; r < 8; r++)                                        \
            h4[r] = *reinterpret_cast<const ulonglong2*>(                  \
                hb + r * 132 + (KK) * 4);                                  \
        ulonglong2 wa = (WA);                                              \
        ulonglong2 wb = (WB);                                              \
        _Pragma("unroll")                                                  \
        for (int r = 0; r < 8; r++) {                                      \
            fma2(acc0[r], wa.x, h4[r].x);                                  \
            fma2(acc0[r], wa.y, h4[r].y);                                  \
            fma2(acc1[r], wb.x, h4[r].x);                                  \
            fma2(acc1[r], wb.y, h4[r].y);                                  \
        }                                                                  \
    }

__global__ void __launch_bounds__(512, 1)
lstm_kernel(const float* __restrict__ ctx,
            const float* __restrict__ Wout,
            const float* __restrict__ bout,
            int T,
            float* __restrict__ out) {
    extern __shared__ float smem[];
    float* sW   = smem;
    float* sh   = smem + SW_FLOATS;
    float* gb   = sh + SH_FLOATS;
    float* sWoT = gb + GB_FLOATS;

    const int tid   = threadIdx.x;
    const int hidx  = tid & 127;
    const int w     = tid >> 7;       // 0..3
    const int ghalf = w >> 1;         // 0: gates i,f   1: gates g,o
    const int khalf = w & 1;          // k range half
    const int r0    = blockIdx.x * 8; // global batch row base

    // stage weights for gates 0..2 into SMEM (float4 copy)
    {
        const float4* src = reinterpret_cast<const float4*>(g_Wc);
        float4* dst = reinterpret_cast<float4*>(sW);
        for (int i = tid; i < 3 * 32 * 128; i += 512) dst[i] = src[i];
    }

    // h0 = context_seq[:, S-1, :]
    for (int i = tid; i < 8 * 128; i += 512) {
        int r = i >> 7, k = i & 127;
        sh[r * 132 + k] = ctx[((size_t)(r0 + r) * S_ + (S_ - 1)) * H_ + k];
    }

    // W_out transposed into SMEM: sWoT[m*28 + (po*4+pp)] = Wout[po*128+pp+4m]
    for (int i = tid; i < 896; i += 512) {
        int m = i / 28, j = i - m * 28;
        int po = j >> 2, pp = j & 3;
        sWoT[i] = Wout[po * 128 + pp + 4 * m];
    }

    // projection thread setup: tid<224 -> (row pr, out po, k-part pp)
    int pr = 0, po = 0, pp = 0, jj = 0;
    float pbo = 0.f;
    const bool isproj = (tid < 224);
    if (isproj) {
        pr = tid / 28;
        jj = tid - pr * 28;
        po = jj >> 2;
        pp = jj & 3;
        pbo = bout[po];
    }

    // this thread's two gate biases (i/f for ghalf0, g/o for ghalf1)
    const float biasA = g_bc[(ghalf ? 256 : 0)   + hidx];
    const float biasB = g_bc[(ghalf ? 384 : 128) + hidx];
    // c-state: this thread owns rows 2w, 2w+1
    float cc0 = 0.f, cc1 = 0.f;

    __syncthreads();

    const ulonglong2* sWp = reinterpret_cast<const ulonglong2*>(sW);
    const ulonglong2* gWo =
        reinterpret_cast<const ulonglong2*>(g_Wc + 3 * 32 * 128 * 4);

    const int kbase = khalf * 16;
    int buf = 0;
    for (int t = 0; t < T; t++) {
        unsigned long long acc0[8], acc1[8];  // [row], packed f32x2
        #pragma unroll
        for (int r = 0; r < 8; r++) { acc0[r] = 0ull; acc1[r] = 0ull; }

        const float* hb = sh + buf * 8 * 132;

        if (ghalf == 0) {
            #pragma unroll 4
            for (int k4 = 0; k4 < 16; k4++) {
                int kk = kbase + k4;
                GATE_K4(kk, sWp[(0 * 32 + kk) * 128 + hidx],
                            sWp[(1 * 32 + kk) * 128 + hidx]);
            }
        } else {
            #pragma unroll 4
            for (int k4 = 0; k4 < 16; k4++) {
                int kk = kbase + k4;
                GATE_K4(kk, sWp[(2 * 32 + kk) * 128 + hidx],
                            gWo[kk * 128 + hidx]);
            }
        }

        // khalf=1 publishes partials to gb[gate][row][hidx]
        if (khalf == 1) {
            #pragma unroll
            for (int r = 0; r < 8; r++) {
                gb[((ghalf * 2 + 0) * 8 + r) * 128 + hidx] = redu(acc0[r]);
                gb[((ghalf * 2 + 1) * 8 + r) * 128 + hidx] = redu(acc1[r]);
            }
        }
        __syncthreads();  // S1

        // khalf=0 adds its partial + bias (RMW; exclusive cell ownership)
        if (khalf == 0) {
            #pragma unroll
            for (int r = 0; r < 8; r++) {
                int ia = ((ghalf * 2 + 0) * 8 + r) * 128 + hidx;
                int ib = ((ghalf * 2 + 1) * 8 + r) * 128 + hidx;
                gb[ia] = gb[ia] + redu(acc0[r]) + biasA;
                gb[ib] = gb[ib] + redu(acc1[r]) + biasB;
            }
        }
        __syncthreads();  // S2

        // pointwise update: all 16 warps, 2 rows per thread (rows 2w, 2w+1)
        const int nbuf = buf ^ 1;
        {
            int r = 2 * w;
            float I  = sigf(gb[(0 * 8 + r) * 128 + hidx]);
            float F  = sigf(gb[(1 * 8 + r) * 128 + hidx]);
            float G  = tanhf_fast(gb[(2 * 8 + r) * 128 + hidx]);
            float Ov = sigf(gb[(3 * 8 + r) * 128 + hidx]);
            cc0 = F * cc0 + I * G;
            sh[(nbuf * 8 + r) * 132 + hidx] = Ov * tanhf_fast(cc0);

            r = 2 * w + 1;
            I  = sigf(gb[(0 * 8 + r) * 128 + hidx]);
            F  = sigf(gb[(1 * 8 + r) * 128 + hidx]);
            G  = tanhf_fast(gb[(2 * 8 + r) * 128 + hidx]);
            Ov = sigf(gb[(3 * 8 + r) * 128 + hidx]);
            cc1 = F * cc1 + I * G;
            sh[(nbuf * 8 + r) * 132 + hidx] = Ov * tanhf_fast(cc1);
        }
        __syncthreads();  // S3

        // output projection (224 thr): h + W_out from SMEM, conflict-free.
        // No trailing sync needed: sh[nbuf] is read-only until t+1's update,
        // which is fenced by S1/S2 of t+1.
        if (isproj) {
            const float* hr = sh + (nbuf * 8 + pr) * 132 + pp;
            float s0 = 0.f, s1 = 0.f;
            #pragma unroll
            for (int m = 0; m < 32; m += 2) {
                s0 += hr[4 * m]       * sWoT[m * 28 + jj];
                s1 += hr[4 * (m + 1)] * sWoT[(m + 1) * 28 + jj];
            }
            float s = s0 + s1;
            s += __shfl_down_sync(0xffffffffu, s, 2);
            s += __shfl_down_sync(0xffffffffu, s, 1);
            if (pp == 0)
                out[((size_t)(r0 + pr) * T + t) * O_ + po] = s + pbo;
        }
        buf = nbuf;
    }
}

extern "C" void kernel_launch(void* const* d_in, const int* in_sizes, int n_in,
                              void* d_out, int out_size) {
    const float* ctx  = (const float*)d_in[0];
    const float* Wih  = (const float*)d_in[1];
    const float* Whh  = (const float*)d_in[2];
    const float* bih  = (const float*)d_in[3];
    const float* bhh  = (const float*)d_in[4];
    const float* Wout = (const float*)d_in[5];
    const float* bout = (const float*)d_in[6];
    float* out = (float*)d_out;

    // T derived from output size (avoids prediction_len dtype ambiguity)
    int T = out_size / (B_ * O_);

    prep_kernel<<<256, 256>>>(Wih, Whh, bih, bhh);

    size_t smem_bytes = (size_t)SMEM_FLOATS * sizeof(float);
    cudaFuncSetAttribute(lstm_kernel,
                         cudaFuncAttributeMaxDynamicSharedMemorySize,
                         (int)smem_bytes);
    lstm_kernel<<<B_ / 8, 512, smem_bytes>>>(ctx, Wout, bout, T, out);
}

// round 12
// speedup vs baseline: 1.5973x; 1.5973x over previous
#include <cuda_runtime.h>
#include <cuda_bf16.h>

// LSTM decoder, B=1024, S=256, H=128, O=7, T=512.
//  - gates = h @ (W_ih + W_hh).T + (b_ih + b_hh)   (both matmuls use h!)
//  - recurrence independent across batch -> persistent kernel, no global sync.
//
// Split-K occupancy kernel, spill-free inner loop.
// 128 CTAs x 512 threads (16 warps, 4/SMSP). Thread (hidx, ghalf, khalf):
// TWO gates for hidden unit hidx over 8 batch rows, HALF the k range:
//   ghalf 0: gates i,f (SMEM weights)   ghalf 1: gate g (SMEM) + o (L2 stream)
// Inner loop streams h one row at a time (single live h register) and caps
// unroll at 2 so ptxas stays under the 128-reg cap WITHOUT local spills
// (R8's h4[8] + unroll-4 spilled and cost +55% dur).
// Partials combined in SMEM gb[gate][row][hidx]: khalf=1 writes, khalf=0
// RMW-adds + bias. Pointwise update over all 16 warps (2 rows/thread,
// c-state in registers). Projection (224 thr) reads h + transposed W_out
// from SMEM, conflict-free.

#define B_   1024
#define S_   256
#define H_   128
#define O_   7

// combined weights in [gate][k4][hidx][kk] layout (k packed in float4)
__device__ float g_Wc[4 * 32 * 128 * 4];
__device__ float g_bc[512];

__global__ void prep_kernel(const float* __restrict__ Wih,
                            const float* __restrict__ Whh,
                            const float* __restrict__ bih,
                            const float* __restrict__ bhh) {
    int idx = blockIdx.x * blockDim.x + threadIdx.x;  // over 512*128
    if (idx < 512 * 128) {
        int j = idx >> 7;        // gate-row 0..511
        int k = idx & 127;       // input hidden idx
        float w = Wih[idx] + Whh[idx];
        int g = j >> 7;
        int h = j & 127;
        g_Wc[(((g * 32) + (k >> 2)) * 128 + h) * 4 + (k & 3)] = w;
    }
    if (idx < 512) g_bc[idx] = bih[idx] + bhh[idx];
}

__device__ __forceinline__ void fma2(unsigned long long& d,
                                     unsigned long long a,
                                     unsigned long long b) {
    asm("fma.rn.f32x2 %0, %1, %2, %0;" : "+l"(d) : "l"(a), "l"(b));
}

__device__ __forceinline__ float redu(unsigned long long v) {
    float2 f = *reinterpret_cast<float2*>(&v);
    return f.x + f.y;
}

__device__ __forceinline__ float sigf(float x) {
    // 1/(1+e^-x): safe at both extremes
    return __fdividef(1.0f, 1.0f + __expf(-x));
}

__device__ __forceinline__ float tanhf_fast(float x) {
    // 1 - 2/(e^{2x}+1): safe at both extremes
    return 1.0f - __fdividef(2.0f, __expf(2.0f * x) + 1.0f);
}

// dynamic smem layout (floats):
//   sW   : 3*32*128*4 = 49152  (gates i,f,g weights)
//   sh   : 2*8*132    = 2112   (double-buffered h, padded stride 132)
//   gb   : 4*8*128    = 4096   (gate values: [gate][row][hidx])
//   sWoT : 32*28      = 896    (W_out transposed: [m][po*4+ppart])
#define SW_FLOATS  49152
#define SH_FLOATS  2112
#define GB_FLOATS  4096
#define SWO_FLOATS 896
#define SMEM_FLOATS (SW_FLOATS + SH_FLOATS + GB_FLOATS + SWO_FLOATS)

__global__ void __launch_bounds__(512, 1)
lstm_kernel(const float* __restrict__ ctx,
            const float* __restrict__ Wout,
            const float* __restrict__ bout,
            int T,
            float* __restrict__ out) {
    extern __shared__ float smem[];
    float* sW   = smem;
    float* sh   = smem + SW_FLOATS;
    float* gb   = sh + SH_FLOATS;
    float* sWoT = gb + GB_FLOATS;

    const int tid   = threadIdx.x;
    const int hidx  = tid & 127;
    const int w     = tid >> 7;       // 0..3
    const int ghalf = w >> 1;         // 0: gates i,f   1: gates g,o
    const int khalf = w & 1;          // k range half
    const int r0    = blockIdx.x * 8; // global batch row base

    // stage weights for gates 0..2 into SMEM (float4 copy)
    {
        const float4* src = reinterpret_cast<const float4*>(g_Wc);
        float4* dst = reinterpret_cast<float4*>(sW);
        for (int i = tid; i < 3 * 32 * 128; i += 512) dst[i] = src[i];
    }

    // h0 = context_seq[:, S-1, :]
    for (int i = tid; i < 8 * 128; i += 512) {
        int r = i >> 7, k = i & 127;
        sh[r * 132 + k] = ctx[((size_t)(r0 + r) * S_ + (S_ - 1)) * H_ + k];
    }

    // W_out transposed into SMEM: sWoT[m*28 + (po*4+pp)] = Wout[po*128+pp+4m]
    for (int i = tid; i < 896; i += 512) {
        int m = i / 28, j = i - m * 28;
        int po = j >> 2, pp = j & 3;
        sWoT[i] = Wout[po * 128 + pp + 4 * m];
    }

    // projection thread setup: tid<224 -> (row pr, out po, k-part pp)
    int pr = 0, po = 0, pp = 0, jj = 0;
    float pbo = 0.f;
    const bool isproj = (tid < 224);
    if (isproj) {
        pr = tid / 28;
        jj = tid - pr * 28;
        po = jj >> 2;
        pp = jj & 3;
        pbo = bout[po];
    }

    // this thread's two gate biases (i/f for ghalf0, g/o for ghalf1)
    const float biasA = g_bc[(ghalf ? 256 : 0)   + hidx];
    const float biasB = g_bc[(ghalf ? 384 : 128) + hidx];
    // c-state: this thread owns rows 2w, 2w+1
    float cc0 = 0.f, cc1 = 0.f;

    __syncthreads();

    // per-thread weight row bases, hoisted (cuts per-iter ALU)
    const ulonglong2* sWp = reinterpret_cast<const ulonglong2*>(sW);
    const ulonglong2* gWo =
        reinterpret_cast<const ulonglong2*>(g_Wc + 3 * 32 * 128 * 4);
    const int kbase = khalf * 16;
    const ulonglong2* wArow;  // gate A weights at k4=kbase, step 128
    const ulonglong2* wBrow;  // gate B weights
    if (ghalf == 0) {
        wArow = sWp + (0 * 32 + kbase) * 128 + hidx;
        wBrow = sWp + (1 * 32 + kbase) * 128 + hidx;
    } else {
        wArow = sWp + (2 * 32 + kbase) * 128 + hidx;
        wBrow = gWo + kbase * 128 + hidx;
    }

    int buf = 0;
    for (int t = 0; t < T; t++) {
        unsigned long long acc0[8], acc1[8];  // [row], packed f32x2
        #pragma unroll
        for (int r = 0; r < 8; r++) { acc0[r] = 0ull; acc1[r] = 0ull; }

        const float* hb = sh + buf * 8 * 132 + kbase * 4;

        // spill-free inner loop: one h row live at a time, unroll capped at 2
        #pragma unroll 2
        for (int k4 = 0; k4 < 16; k4++) {
            ulonglong2 wa = wArow[k4 * 128];
            ulonglong2 wb = wBrow[k4 * 128];
            const float* hk = hb + k4 * 4;
            #pragma unroll
            for (int r = 0; r < 8; r++) {
                ulonglong2 h4 =
                    *reinterpret_cast<const ulonglong2*>(hk + r * 132);
                fma2(acc0[r], wa.x, h4.x);
                fma2(acc0[r], wa.y, h4.y);
                fma2(acc1[r], wb.x, h4.x);
                fma2(acc1[r], wb.y, h4.y);
            }
        }

        // khalf=1 publishes partials to gb[gate][row][hidx]
        if (khalf == 1) {
            #pragma unroll
            for (int r = 0; r < 8; r++) {
                gb[((ghalf * 2 + 0) * 8 + r) * 128 + hidx] = redu(acc0[r]);
                gb[((ghalf * 2 + 1) * 8 + r) * 128 + hidx] = redu(acc1[r]);
            }
        }
        __syncthreads();  // S1

        // khalf=0 adds its partial + bias (RMW; exclusive cell ownership)
        if (khalf == 0) {
            #pragma unroll
            for (int r = 0; r < 8; r++) {
                int ia = ((ghalf * 2 + 0) * 8 + r) * 128 + hidx;
                int ib = ((ghalf * 2 + 1) * 8 + r) * 128 + hidx;
                gb[ia] = gb[ia] + redu(acc0[r]) + biasA;
                gb[ib] = gb[ib] + redu(acc1[r]) + biasB;
            }
        }
        __syncthreads();  // S2

        // pointwise update: all 16 warps, 2 rows per thread (rows 2w, 2w+1)
        const int nbuf = buf ^ 1;
        {
            int r = 2 * w;
            float I  = sigf(gb[(0 * 8 + r) * 128 + hidx]);
            float F  = sigf(gb[(1 * 8 + r) * 128 + hidx]);
            float G  = tanhf_fast(gb[(2 * 8 + r) * 128 + hidx]);
            float Ov = sigf(gb[(3 * 8 + r) * 128 + hidx]);
            cc0 = F * cc0 + I * G;
            sh[(nbuf * 8 + r) * 132 + hidx] = Ov * tanhf_fast(cc0);

            r = 2 * w + 1;
            I  = sigf(gb[(0 * 8 + r) * 128 + hidx]);
            F  = sigf(gb[(1 * 8 + r) * 128 + hidx]);
            G  = tanhf_fast(gb[(2 * 8 + r) * 128 + hidx]);
            Ov = sigf(gb[(3 * 8 + r) * 128 + hidx]);
            cc1 = F * cc1 + I * G;
            sh[(nbuf * 8 + r) * 132 + hidx] = Ov * tanhf_fast(cc1);
        }
        __syncthreads();  // S3

        // output projection (224 thr): h + W_out from SMEM, conflict-free.
        // No trailing sync needed: sh[nbuf] is read-only until t+1's update,
        // which is fenced by S1/S2 of t+1.
        if (isproj) {
            const float* hr = sh + (nbuf * 8 + pr) * 132 + pp;
            float s0 = 0.f, s1 = 0.f;
            #pragma unroll
            for (int m = 0; m < 32; m += 2) {
                s0 += hr[4 * m]       * sWoT[m * 28 + jj];
                s1 += hr[4 * (m + 1)] * sWoT[(m + 1) * 28 + jj];
            }
            float s = s0 + s1;
            s += __shfl_down_sync(0xffffffffu, s, 2);
            s += __shfl_down_sync(0xffffffffu, s, 1);
            if (pp == 0)
                out[((size_t)(r0 + pr) * T + t) * O_ + po] = s + pbo;
        }
        buf = nbuf;
    }
}

extern "C" void kernel_launch(void* const* d_in, const int* in_sizes, int n_in,
                              void* d_out, int out_size) {
    const float* ctx  = (const float*)d_in[0];
    const float* Wih  = (const float*)d_in[1];
    const float* Whh  = (const float*)d_in[2];
    const float* bih  = (const float*)d_in[3];
    const float* bhh  = (const float*)d_in[4];
    const float* Wout = (const float*)d_in[5];
    const float* bout = (const float*)d_in[6];
    float* out = (float*)d_out;

    // T derived from output size (avoids prediction_len dtype ambiguity)
    int T = out_size / (B_ * O_);

    prep_kernel<<<256, 256>>>(Wih, Whh, bih, bhh);

    size_t smem_bytes = (size_t)SMEM_FLOATS * sizeof(float);
    cudaFuncSetAttribute(lstm_kernel,
                         cudaFuncAttributeMaxDynamicSharedMemorySize,
                         (int)smem_bytes);
    lstm_kernel<<<B_ / 8, 512, smem_bytes>>>(ctx, Wout, bout, T, out);
}